// round 11
// baseline (speedup 1.0000x reference)
#include <cuda_runtime.h>
#include <stdint.h>

#define B_   4096
#define F_   1024
#define H_   256
#define C_   10
#define T_   24
#define T2   (T_ - 2)     // 22 real steps; 22/23 gathers are dead
#define RPB  4

// ---- transposed weights (device globals; no allocation) ----
__device__ __align__(16) float g_W1T[F_ * H_];   // [f][j]
__device__ __align__(16) float g_W2T[H_ * H_];   // [k][j]
__device__ __align__(16) float g_W3T[H_ * H_];   // [k][j]

// ---- packed f32x2 helpers (Blackwell) ----
__device__ __forceinline__ unsigned long long pk2(float lo, float hi) {
    unsigned long long r;
    asm("mov.b64 %0, {%1, %2};" : "=l"(r) : "f"(lo), "f"(hi));
    return r;
}
__device__ __forceinline__ void upk2(unsigned long long v, float& lo, float& hi) {
    asm("mov.b64 {%0, %1}, %2;" : "=f"(lo), "=f"(hi) : "l"(v));
}
__device__ __forceinline__ void addx2(unsigned long long& a, unsigned long long b) {
    asm("add.rn.f32x2 %0, %1, %2;" : "=l"(a) : "l"(a), "l"(b));
}

// per-row-group barrier (64 threads, ids 1..RPB)
#define BARG() asm volatile("bar.sync %0, 64;" :: "r"(barid) : "memory")

// ============================================================
// Tiled transpose of W1/W2/W3 into device globals.
// ============================================================
__global__ void __launch_bounds__(256) transpose_all(
    const float* __restrict__ W1, const float* __restrict__ W2,
    const float* __restrict__ W3) {
    __shared__ float tile[32][33];
    const int zi = blockIdx.z;
    const float* src = (zi == 0) ? W1 : ((zi == 1) ? W2 : W3);
    float* dst = (zi == 0) ? g_W1T : ((zi == 1) ? g_W2T : g_W3T);
    const int C = (zi == 0) ? F_ : H_;
    const int R = H_;
    if ((int)(blockIdx.x * 32) >= C) return;

    const int x = blockIdx.x * 32 + threadIdx.x;
    const int y0 = blockIdx.y * 32;
#pragma unroll
    for (int dy = threadIdx.y; dy < 32; dy += 8)
        tile[dy][threadIdx.x] = src[(size_t)(y0 + dy) * C + x];
    __syncthreads();
    const int x2 = y0 + threadIdx.x;
#pragma unroll
    for (int dy = threadIdx.y; dy < 32; dy += 8)
        dst[(size_t)(blockIdx.x * 32 + dy) * R + x2] = tile[threadIdx.x][dy];
}

// ============================================================
// gather over prescaled byte offsets, 4 accumulator chains, unroll 4
// ============================================================
__device__ __forceinline__ void gatherN(const char* __restrict__ wb,
                                        const uint32_t* __restrict__ lst, int n,
                                        unsigned long long& a01, unsigned long long& a23,
                                        unsigned long long& b01, unsigned long long& b23) {
    int e = 0;
    for (; e + 4 <= n; e += 4) {
        uint4 o = *(const uint4*)(lst + e);
        ulonglong2 w0 = *(const ulonglong2*)(wb + o.x);
        ulonglong2 w1 = *(const ulonglong2*)(wb + o.y);
        ulonglong2 w2 = *(const ulonglong2*)(wb + o.z);
        ulonglong2 w3 = *(const ulonglong2*)(wb + o.w);
        addx2(a01, w0.x); addx2(a23, w0.y);
        addx2(b01, w1.x); addx2(b23, w1.y);
        addx2(a01, w2.x); addx2(a23, w2.y);
        addx2(b01, w3.x); addx2(b23, w3.y);
    }
    for (; e < n; e++) {
        ulonglong2 w = *(const ulonglong2*)(wb + lst[e]);
        addx2(a01, w.x); addx2(a23, w.y);
    }
}

// ============================================================
// Main fused kernel (R7 skeleton) with the W1 gather hoisted:
// phase 1 is pure ALU (LIF1 + z1 append + next enc-list build);
// phase 3 runs ONE fused loop gathering W3[o2_t] and W1[enc_{t+1}]
// with interleaved loads (2x MLP), result carried to next step.
// Dead steps 22/23 remain elided.
// ============================================================
__global__ void __launch_bounds__(256, 4)
snn_kernel(const float* __restrict__ x,
           const float* __restrict__ b1, const float* __restrict__ b2,
           const float* __restrict__ b3, const float* __restrict__ Wli,
           float* __restrict__ out) {
    __shared__ uint32_t s_bits[RPB][T_][32];                 // 12 KB
    __shared__ __align__(16) uint16_t s_l1[2][RPB][512];     // 8 KB (enc lists, dbl-buf)
    __shared__ __align__(16) uint32_t s_lh[2][RPB][2 * H_];  // 16 KB (z1 then z2 offsets)
    __shared__ int s_cntA[2][RPB];
    __shared__ int s_cnt1[2][RPB];
    __shared__ int s_cnt2[2][RPB];
    __shared__ float s_part[RPB][2][C_];

    const int tid = threadIdx.x;
    const int r = tid >> 6;
    const int g = tid & 63;
    const int lane = tid & 31;
    const int j0 = g * 4;
    const int barid = r + 1;
    const int row = blockIdx.x * RPB + r;
    const float* xrow = x + (size_t)row * F_;

    // ---- zero this row's bitmaps & counters ----
    for (int i = g; i < T_ * 32; i += 64) ((uint32_t*)s_bits[r])[i] = 0;
    if (g == 0) {
        s_cntA[0][r] = 0; s_cntA[1][r] = 0;
        s_cnt1[0][r] = 0; s_cnt1[1][r] = 0;
        s_cnt2[0][r] = 0; s_cnt2[1][r] = 0;
    }
    BARG();

    // ---- fused encoder -> scatter spikes into per-step bitmaps ----
    {
        const uint32_t mybit = 1u << (g & 31);
        const int wbase = g >> 5;
#pragma unroll 1
        for (int m0 = 0; m0 < 16; m0 += 4) {
            float xv[4], vv[4];
            uint32_t mk[4];
#pragma unroll
            for (int j = 0; j < 4; j++) {
                xv[j] = xrow[g + 64 * (m0 + j)];
                vv[j] = 0.0f; mk[j] = 0u;
            }
#pragma unroll
            for (int t = 0; t < T_; t++) {
#pragma unroll
                for (int j = 0; j < 4; j++) {
                    vv[j] = vv[j] + 0.1f * (xv[j] - vv[j]);
                    if (vv[j] > 1.0f) { mk[j] |= (1u << t); vv[j] = 0.0f; }
                }
            }
#pragma unroll
            for (int j = 0; j < 4; j++) {
                uint32_t m = mk[j];
                const int w = wbase + 2 * (m0 + j);
                while (m) {
                    int t = __ffs(m) - 1; m &= m - 1;
                    atomicOr(&s_bits[r][t][w], mybit);
                }
            }
        }
    }
    BARG();

    // ---- prologue: build enc list for t=0 into buffer 1 ----
    if (g < 32) {
        uint32_t w = s_bits[r][0][g];
        while (w) {
            int b = __ffs(w) - 1; w &= w - 1;
            int p = atomicAdd(&s_cntA[1][r], 1);
            s_l1[1][r][p] = (uint16_t)((g << 5) | b);
        }
    }
    BARG();

    const char* W1b = (const char*)g_W1T + (size_t)j0 * 4;
    const char* W2b = (const char*)g_W2T + (size_t)j0 * 4;
    const char* W3b = (const char*)g_W3T + (size_t)j0 * 4;

    // ---- prologue gather: accW1 = W1[enc_0] + b1 ----
    unsigned long long aw01, aw23;
    {
        float4 bv = *(const float4*)(b1 + j0);
        aw01 = pk2(bv.x, bv.y); aw23 = pk2(bv.z, bv.w);
        unsigned long long d01 = pk2(0.f, 0.f), d23 = pk2(0.f, 0.f);
        const uint16_t* lst = s_l1[1][r];
        const int n = s_cntA[1][r];
        int e = 0;
        for (; e + 2 <= n; e += 2) {
            ulonglong2 w0 = *(const ulonglong2*)(W1b + ((uint32_t)lst[e] << 10));
            ulonglong2 w1 = *(const ulonglong2*)(W1b + ((uint32_t)lst[e + 1] << 10));
            addx2(aw01, w0.x); addx2(aw23, w0.y);
            addx2(d01, w1.x);  addx2(d23, w1.y);
        }
        if (e < n) {
            ulonglong2 w = *(const ulonglong2*)(W1b + ((uint32_t)lst[e] << 10));
            addx2(aw01, w.x); addx2(aw23, w.y);
        }
        addx2(aw01, d01); addx2(aw23, d23);
    }

    float v1[4] = {0,0,0,0}, i1[4] = {0,0,0,0};
    float v2[4] = {0,0,0,0}, i2[4] = {0,0,0,0};
    float v3[4] = {0,0,0,0}, i3[4] = {0,0,0,0};
    float q[4]  = {0,0,0,0};
    float z1f[4], z2f[4];

    // readout coefficients: coef_t = 0.9^(23-t) - 0.8^(23-t)
    float c9 = 1.0f, c8 = 1.0f;
#pragma unroll
    for (int i = 0; i < T_ - 1; i++) { c9 *= 0.9f; c8 *= 0.8f; }

    int par = 0;

#pragma unroll 1
    for (int t = 0; t < T2; t++) {
        // ===== phase 1 (no gather): LIF1 from carried accW1; z1 append;
        //       build enc list for t+1 from static bitmap =====
        {
            float a[4]; upk2(aw01, a[0], a[1]); upk2(aw23, a[2], a[3]);
            int* cnt = &s_cnt1[par][r];
            uint32_t* dl = s_lh[par][r];
#pragma unroll
            for (int u = 0; u < 4; u++) {
                float vd = v1[u] + 0.1f * (i1[u] - v1[u]);
                i1[u] = i1[u] * 0.8f + a[u];
                bool z = vd > 0.23f;
                v1[u] = z ? 0.0f : vd;
                z1f[u] = z ? 1.0f : 0.0f;
                if (z) { int p = atomicAdd(cnt, 1); dl[p] = (uint32_t)((j0 + u) << 10); }
            }
            if (t < T2 - 1 && g < 32) {
                uint32_t w = s_bits[r][t + 1][g];
                while (w) {
                    int b = __ffs(w) - 1; w &= w - 1;
                    int p = atomicAdd(&s_cntA[par][r], 1);
                    s_l1[par][r][p] = (uint16_t)((g << 5) | b);
                }
            }
        }
        BARG();

        // ================= phase 2: layer 2 (W2 gather) =================
        {
            if (g == 0) {       // opposite-parity buffers untouched this phase
                s_cntA[par ^ 1][r] = 0;
                s_cnt1[par ^ 1][r] = 0;
                s_cnt2[par ^ 1][r] = 0;
            }
            float4 bv = *(const float4*)(b2 + j0);
            unsigned long long a01 = pk2(bv.x, bv.y), a23 = pk2(bv.z, bv.w);
            unsigned long long b01 = pk2(0.f, 0.f),   b23 = pk2(0.f, 0.f);
            const int nA = s_cnt1[par][r];          // stable all phase
            gatherN(W2b, s_lh[par][r], nA, a01, a23, b01, b23);
            addx2(a01, b01); addx2(a23, b23);
            float a[4]; upk2(a01, a[0], a[1]); upk2(a23, a[2], a[3]);
            int* cnt = &s_cnt2[par][r];
            uint32_t* dl = s_lh[par][r];
#pragma unroll
            for (int u = 0; u < 4; u++) {
                float vd = v2[u] + 0.1f * (i2[u] - v2[u]);
                i2[u] = i2[u] * 0.8f + a[u];
                bool z = vd > 0.23f;
                v2[u] = z ? 0.0f : vd;
                z2f[u] = z ? 1.0f : 0.0f;
                if (z) { int p = nA + atomicAdd(cnt, 1); dl[p] = (uint32_t)((j0 + u) << 10); }
            }
        }
        BARG();

        // ===== phase 3: FUSED gather W3[z1+z2] + W1[enc_{t+1}] (interleaved
        //       loads, 2x MLP); LIF3 + readout fold; carry accW1 =====
        {
            float4 bv3 = *(const float4*)(b3 + j0);
            float4 bv1 = *(const float4*)(b1 + j0);
            unsigned long long c01 = pk2(bv3.x, bv3.y), c23 = pk2(bv3.z, bv3.w);
            unsigned long long w01 = pk2(bv1.x, bv1.y), w23 = pk2(bv1.z, bv1.w);
            const int nC = s_cnt1[par][r] + s_cnt2[par][r];  // o2 = z1 + z2
            const int nW = (t < T2 - 1) ? s_cntA[par][r] : 0;
            const uint32_t* lc = s_lh[par][r];
            const uint16_t* lw = s_l1[par][r];
            const int nmax = (nC > nW) ? nC : nW;
#pragma unroll 2
            for (int e = 0; e < nmax; e++) {
                if (e < nC) {
                    ulonglong2 w = *(const ulonglong2*)(W3b + lc[e]);
                    addx2(c01, w.x); addx2(c23, w.y);
                }
                if (e < nW) {
                    ulonglong2 w = *(const ulonglong2*)(W1b + ((uint32_t)lw[e] << 10));
                    addx2(w01, w.x); addx2(w23, w.y);
                }
            }
            aw01 = w01; aw23 = w23;
            float a[4]; upk2(c01, a[0], a[1]); upk2(c23, a[2], a[3]);
            float coef = c9 - c8;
            c9 *= (1.0f / 0.9f);
            c8 *= 1.25f;
#pragma unroll
            for (int u = 0; u < 4; u++) {
                float vd = v3[u] + 0.1f * (i3[u] - v3[u]);
                i3[u] = i3[u] * 0.8f + a[u];
                bool z = vd > 0.23f;
                v3[u] = z ? 0.0f : vd;
                float o3 = (z ? 1.0f : 0.0f) + z1f[u] + z2f[u];
                q[u] = fmaf(coef, o3, q[u]);
            }
        }
        BARG();
        par ^= 1;
    }

    // ===== step 22 epilogue: all gathers dead; spikes from local state only =====
    {
        float coef = c9 - c8;   // = 0.9 - 0.8 = 0.1
#pragma unroll
        for (int u = 0; u < 4; u++) {
            float vd1 = v1[u] + 0.1f * (i1[u] - v1[u]);
            float vd2 = v2[u] + 0.1f * (i2[u] - v2[u]);
            float vd3 = v3[u] + 0.1f * (i3[u] - v3[u]);
            float o3 = (vd1 > 0.23f ? 1.0f : 0.0f)
                     + (vd2 > 0.23f ? 1.0f : 0.0f)
                     + (vd3 > 0.23f ? 1.0f : 0.0f);
            q[u] = fmaf(coef, o3, q[u]);
        }
    }
    // step 23: output coefficient is exactly 0 -> nothing to do.

    // ---- final readout: out[b][c] = sum_k q_k * Wli[c][k] ----
    const int wig = (tid >> 5) & 1;
#pragma unroll
    for (int c = 0; c < C_; c++) {
        float4 w = *(const float4*)(Wli + c * H_ + j0);
        float s = q[0] * w.x + q[1] * w.y + q[2] * w.z + q[3] * w.w;
#pragma unroll
        for (int off = 16; off; off >>= 1)
            s += __shfl_xor_sync(0xffffffffu, s, off);
        if (lane == 0) s_part[r][wig][c] = s;
    }
    BARG();
    if (g < C_) out[(size_t)row * C_ + g] = s_part[r][0][g] + s_part[r][1][g];
}

// ============================================================
extern "C" void kernel_launch(void* const* d_in, const int* in_sizes, int n_in,
                              void* d_out, int out_size) {
    (void)in_sizes; (void)n_in; (void)out_size;
    const float* x   = (const float*)d_in[0];
    const float* W1  = (const float*)d_in[1];
    const float* b1  = (const float*)d_in[2];
    const float* W2  = (const float*)d_in[3];
    const float* b2  = (const float*)d_in[4];
    const float* W3  = (const float*)d_in[5];
    const float* b3  = (const float*)d_in[6];
    const float* Wli = (const float*)d_in[7];
    float* out = (float*)d_out;

    transpose_all<<<dim3(F_ / 32, H_ / 32, 3), dim3(32, 8)>>>(W1, W2, W3);
    snn_kernel<<<B_ / RPB, 256>>>(x, b1, b2, b3, Wli, out);
}

// round 12
// speedup vs baseline: 1.8341x; 1.8341x over previous
#include <cuda_runtime.h>
#include <stdint.h>

#define B_   4096
#define F_   1024
#define H_   256
#define C_   10
#define T_   24
#define T2   (T_ - 2)     // steps 22/23 gathers are dead
#define RPB  4

// ---- transposed weights (device globals; no allocation) ----
__device__ __align__(16) float g_W1T[F_ * H_];   // [f][j]
__device__ __align__(16) float g_W2T[H_ * H_];   // [k][j]
__device__ __align__(16) float g_W3T[H_ * H_];   // [k][j]

// ---- packed f32x2 helpers (Blackwell) ----
__device__ __forceinline__ unsigned long long pk2(float lo, float hi) {
    unsigned long long r;
    asm("mov.b64 %0, {%1, %2};" : "=l"(r) : "f"(lo), "f"(hi));
    return r;
}
__device__ __forceinline__ void upk2(unsigned long long v, float& lo, float& hi) {
    asm("mov.b64 {%0, %1}, %2;" : "=f"(lo), "=f"(hi) : "l"(v));
}
__device__ __forceinline__ void addx2(unsigned long long& a, unsigned long long b) {
    asm("add.rn.f32x2 %0, %1, %2;" : "=l"(a) : "l"(a), "l"(b));
}

// per-row-group barrier (64 threads, ids 1..RPB)
#define BARG() asm volatile("bar.sync %0, 64;" :: "r"(barid) : "memory")

// ============================================================
// Tiled transpose of W1/W2/W3 into device globals.
// ============================================================
__global__ void __launch_bounds__(256) transpose_all(
    const float* __restrict__ W1, const float* __restrict__ W2,
    const float* __restrict__ W3) {
    __shared__ float tile[32][33];
    const int zi = blockIdx.z;
    const float* src = (zi == 0) ? W1 : ((zi == 1) ? W2 : W3);
    float* dst = (zi == 0) ? g_W1T : ((zi == 1) ? g_W2T : g_W3T);
    const int C = (zi == 0) ? F_ : H_;
    const int R = H_;
    if ((int)(blockIdx.x * 32) >= C) return;

    const int x = blockIdx.x * 32 + threadIdx.x;
    const int y0 = blockIdx.y * 32;
#pragma unroll
    for (int dy = threadIdx.y; dy < 32; dy += 8)
        tile[dy][threadIdx.x] = src[(size_t)(y0 + dy) * C + x];
    __syncthreads();
    const int x2 = y0 + threadIdx.x;
#pragma unroll
    for (int dy = threadIdx.y; dy < 32; dy += 8)
        dst[(size_t)(blockIdx.x * 32 + dy) * R + x2] = tile[threadIdx.x][dy];
}

// ============================================================
// gather over prescaled byte offsets, 4 accumulator chains, unroll 4
// (PROVEN codegen — do not restructure)
// ============================================================
__device__ __forceinline__ void gatherN(const char* __restrict__ wb,
                                        const uint32_t* __restrict__ lst, int n,
                                        unsigned long long& a01, unsigned long long& a23,
                                        unsigned long long& b01, unsigned long long& b23) {
    int e = 0;
    for (; e + 4 <= n; e += 4) {
        uint4 o = *(const uint4*)(lst + e);
        ulonglong2 w0 = *(const ulonglong2*)(wb + o.x);
        ulonglong2 w1 = *(const ulonglong2*)(wb + o.y);
        ulonglong2 w2 = *(const ulonglong2*)(wb + o.z);
        ulonglong2 w3 = *(const ulonglong2*)(wb + o.w);
        addx2(a01, w0.x); addx2(a23, w0.y);
        addx2(b01, w1.x); addx2(b23, w1.y);
        addx2(a01, w2.x); addx2(a23, w2.y);
        addx2(b01, w3.x); addx2(b23, w3.y);
    }
    for (; e < n; e++) {
        ulonglong2 w = *(const ulonglong2*)(wb + lst[e]);
        addx2(a01, w.x); addx2(a23, w.y);
    }
}

// ============================================================
// Main fused kernel (R7 skeleton) with a PROPER W1 hoist:
// phase 3 runs TWO back-to-back gatherN loops (W3[o2_t], then
// W1[enc_{t+1}] into carried accumulators) -> phase 1 is pure ALU.
// Enc lists are prescaled-u32, double-buffered, built in phase 2.
// Dead steps 22/23 elided.
// ============================================================
__global__ void __launch_bounds__(256, 4)
snn_kernel(const float* __restrict__ x,
           const float* __restrict__ b1, const float* __restrict__ b2,
           const float* __restrict__ b3, const float* __restrict__ Wli,
           float* __restrict__ out) {
    __shared__ uint32_t s_bits[RPB][T_][32];                 // 12 KB
    __shared__ __align__(16) uint32_t s_l1e[2][RPB][512];    // 16 KB (enc byte-offset lists)
    __shared__ __align__(16) uint32_t s_lh[2][RPB][2 * H_];  // 16 KB (z1 then z2 offsets)
    __shared__ int s_cntA[2][RPB];
    __shared__ int s_cnt1[2][RPB];
    __shared__ int s_cnt2[2][RPB];
    __shared__ float s_part[RPB][2][C_];

    const int tid = threadIdx.x;
    const int r = tid >> 6;
    const int g = tid & 63;
    const int lane = tid & 31;
    const int j0 = g * 4;
    const int barid = r + 1;
    const int row = blockIdx.x * RPB + r;
    const float* xrow = x + (size_t)row * F_;

    // ---- zero this row's bitmaps & counters ----
    for (int i = g; i < T_ * 32; i += 64) ((uint32_t*)s_bits[r])[i] = 0;
    if (g == 0) {
        s_cntA[0][r] = 0; s_cntA[1][r] = 0;
        s_cnt1[0][r] = 0; s_cnt1[1][r] = 0;
        s_cnt2[0][r] = 0; s_cnt2[1][r] = 0;
    }
    BARG();

    // ---- fused encoder -> scatter spikes into per-step bitmaps ----
    {
        const uint32_t mybit = 1u << (g & 31);
        const int wbase = g >> 5;
#pragma unroll 1
        for (int m0 = 0; m0 < 16; m0 += 4) {
            float xv[4], vv[4];
            uint32_t mk[4];
#pragma unroll
            for (int j = 0; j < 4; j++) {
                xv[j] = xrow[g + 64 * (m0 + j)];
                vv[j] = 0.0f; mk[j] = 0u;
            }
#pragma unroll
            for (int t = 0; t < T_; t++) {
#pragma unroll
                for (int j = 0; j < 4; j++) {
                    vv[j] = vv[j] + 0.1f * (xv[j] - vv[j]);
                    if (vv[j] > 1.0f) { mk[j] |= (1u << t); vv[j] = 0.0f; }
                }
            }
#pragma unroll
            for (int j = 0; j < 4; j++) {
                uint32_t m = mk[j];
                const int w = wbase + 2 * (m0 + j);
                while (m) {
                    int t = __ffs(m) - 1; m &= m - 1;
                    atomicOr(&s_bits[r][t][w], mybit);
                }
            }
        }
    }
    BARG();

    // ---- prologue: build enc list for t=0 into buffer 0 (prescaled offsets) ----
    if (g < 32) {
        uint32_t w = s_bits[r][0][g];
        while (w) {
            int b = __ffs(w) - 1; w &= w - 1;
            int p = atomicAdd(&s_cntA[0][r], 1);
            s_l1e[0][r][p] = (uint32_t)(((g << 5) | b) << 10);
        }
    }
    BARG();

    const char* W1b = (const char*)g_W1T + (size_t)j0 * 4;
    const char* W2b = (const char*)g_W2T + (size_t)j0 * 4;
    const char* W3b = (const char*)g_W3T + (size_t)j0 * 4;

    // ---- prologue gather: aw = W1[enc_0] + b1 (proven gatherN) ----
    unsigned long long aw01, aw23;
    {
        float4 bv = *(const float4*)(b1 + j0);
        aw01 = pk2(bv.x, bv.y); aw23 = pk2(bv.z, bv.w);
        unsigned long long d01 = pk2(0.f, 0.f), d23 = pk2(0.f, 0.f);
        gatherN(W1b, s_l1e[0][r], s_cntA[0][r], aw01, aw23, d01, d23);
        addx2(aw01, d01); addx2(aw23, d23);
    }

    float v1[4] = {0,0,0,0}, i1[4] = {0,0,0,0};
    float v2[4] = {0,0,0,0}, i2[4] = {0,0,0,0};
    float v3[4] = {0,0,0,0}, i3[4] = {0,0,0,0};
    float q[4]  = {0,0,0,0};
    float z1f[4], z2f[4];

    // readout coefficients: coef_t = 0.9^(23-t) - 0.8^(23-t)
    float c9 = 1.0f, c8 = 1.0f;
#pragma unroll
    for (int i = 0; i < T_ - 1; i++) { c9 *= 0.9f; c8 *= 0.8f; }

    int par = 0;

#pragma unroll 1
    for (int t = 0; t < T2; t++) {
        // ===== phase 1 (pure ALU): LIF1 from carried aw; z1 append =====
        {
            if (g == 0) s_cntA[par ^ 1][r] = 0;   // last read: phase 3 of step t-2
            float a[4]; upk2(aw01, a[0], a[1]); upk2(aw23, a[2], a[3]);
            int* cnt = &s_cnt1[par][r];
            uint32_t* dl = s_lh[par][r];
#pragma unroll
            for (int u = 0; u < 4; u++) {
                float vd = v1[u] + 0.1f * (i1[u] - v1[u]);
                i1[u] = i1[u] * 0.8f + a[u];
                bool z = vd > 0.23f;
                v1[u] = z ? 0.0f : vd;
                z1f[u] = z ? 1.0f : 0.0f;
                if (z) { int p = atomicAdd(cnt, 1); dl[p] = (uint32_t)((j0 + u) << 10); }
            }
        }
        BARG();

        // ===== phase 2: W2 gather; LIF2 + z2 append; warp0 builds enc_{t+1} =====
        {
            if (g == 0) {     // opposite-parity hidden lists untouched this phase
                s_cnt1[par ^ 1][r] = 0;
                s_cnt2[par ^ 1][r] = 0;
            }
            float4 bv = *(const float4*)(b2 + j0);
            unsigned long long a01 = pk2(bv.x, bv.y), a23 = pk2(bv.z, bv.w);
            unsigned long long b01 = pk2(0.f, 0.f),   b23 = pk2(0.f, 0.f);
            const int nA = s_cnt1[par][r];          // stable all phase
            gatherN(W2b, s_lh[par][r], nA, a01, a23, b01, b23);
            addx2(a01, b01); addx2(a23, b23);
            float a[4]; upk2(a01, a[0], a[1]); upk2(a23, a[2], a[3]);
            int* cnt = &s_cnt2[par][r];
            uint32_t* dl = s_lh[par][r];
#pragma unroll
            for (int u = 0; u < 4; u++) {
                float vd = v2[u] + 0.1f * (i2[u] - v2[u]);
                i2[u] = i2[u] * 0.8f + a[u];
                bool z = vd > 0.23f;
                v2[u] = z ? 0.0f : vd;
                z2f[u] = z ? 1.0f : 0.0f;
                if (z) { int p = nA + atomicAdd(cnt, 1); dl[p] = (uint32_t)((j0 + u) << 10); }
            }
            // build enc list for t+1 (consumed by phase 3's W1 gather)
            if (t < T2 - 1 && g < 32) {
                uint32_t w = s_bits[r][t + 1][g];
                while (w) {
                    int b = __ffs(w) - 1; w &= w - 1;
                    int p = atomicAdd(&s_cntA[par ^ 1][r], 1);
                    s_l1e[par ^ 1][r][p] = (uint32_t)(((g << 5) | b) << 10);
                }
            }
        }
        BARG();

        // ===== phase 3: W3 gather, then W1[enc_{t+1}] gather (independent
        //       accumulators -> overlapped loads); LIF3 + readout fold =====
        {
            float4 bv3 = *(const float4*)(b3 + j0);
            unsigned long long a01 = pk2(bv3.x, bv3.y), a23 = pk2(bv3.z, bv3.w);
            unsigned long long b01 = pk2(0.f, 0.f),     b23 = pk2(0.f, 0.f);
            const int n = s_cnt1[par][r] + s_cnt2[par][r];   // o2 = z1 + z2
            gatherN(W3b, s_lh[par][r], n, a01, a23, b01, b23);

            // W1 gather for next step (aw carried in registers)
            float4 bv1 = *(const float4*)(b1 + j0);
            aw01 = pk2(bv1.x, bv1.y); aw23 = pk2(bv1.z, bv1.w);
            unsigned long long d01 = pk2(0.f, 0.f), d23 = pk2(0.f, 0.f);
            const int nW = (t < T2 - 1) ? s_cntA[par ^ 1][r] : 0;
            gatherN(W1b, s_l1e[par ^ 1][r], nW, aw01, aw23, d01, d23);
            addx2(aw01, d01); addx2(aw23, d23);

            addx2(a01, b01); addx2(a23, b23);
            float a[4]; upk2(a01, a[0], a[1]); upk2(a23, a[2], a[3]);
            float coef = c9 - c8;
            c9 *= (1.0f / 0.9f);
            c8 *= 1.25f;
#pragma unroll
            for (int u = 0; u < 4; u++) {
                float vd = v3[u] + 0.1f * (i3[u] - v3[u]);
                i3[u] = i3[u] * 0.8f + a[u];
                bool z = vd > 0.23f;
                v3[u] = z ? 0.0f : vd;
                float o3 = (z ? 1.0f : 0.0f) + z1f[u] + z2f[u];
                q[u] = fmaf(coef, o3, q[u]);
            }
        }
        BARG();
        par ^= 1;
    }

    // ===== step 22 epilogue: all gathers dead; spikes from local state only =====
    {
        float coef = c9 - c8;   // = 0.9 - 0.8 = 0.1
#pragma unroll
        for (int u = 0; u < 4; u++) {
            float vd1 = v1[u] + 0.1f * (i1[u] - v1[u]);
            float vd2 = v2[u] + 0.1f * (i2[u] - v2[u]);
            float vd3 = v3[u] + 0.1f * (i3[u] - v3[u]);
            float o3 = (vd1 > 0.23f ? 1.0f : 0.0f)
                     + (vd2 > 0.23f ? 1.0f : 0.0f)
                     + (vd3 > 0.23f ? 1.0f : 0.0f);
            q[u] = fmaf(coef, o3, q[u]);
        }
    }
    // step 23: output coefficient is exactly 0 -> nothing to do.

    // ---- final readout: out[b][c] = sum_k q_k * Wli[c][k] ----
    const int wig = (tid >> 5) & 1;
#pragma unroll
    for (int c = 0; c < C_; c++) {
        float4 w = *(const float4*)(Wli + c * H_ + j0);
        float s = q[0] * w.x + q[1] * w.y + q[2] * w.z + q[3] * w.w;
#pragma unroll
        for (int off = 16; off; off >>= 1)
            s += __shfl_xor_sync(0xffffffffu, s, off);
        if (lane == 0) s_part[r][wig][c] = s;
    }
    BARG();
    if (g < C_) out[(size_t)row * C_ + g] = s_part[r][0][g] + s_part[r][1][g];
}

// ============================================================
extern "C" void kernel_launch(void* const* d_in, const int* in_sizes, int n_in,
                              void* d_out, int out_size) {
    (void)in_sizes; (void)n_in; (void)out_size;
    const float* x   = (const float*)d_in[0];
    const float* W1  = (const float*)d_in[1];
    const float* b1  = (const float*)d_in[2];
    const float* W2  = (const float*)d_in[3];
    const float* b2  = (const float*)d_in[4];
    const float* W3  = (const float*)d_in[5];
    const float* b3  = (const float*)d_in[6];
    const float* Wli = (const float*)d_in[7];
    float* out = (float*)d_out;

    transpose_all<<<dim3(F_ / 32, H_ / 32, 3), dim3(32, 8)>>>(W1, W2, W3);
    snn_kernel<<<B_ / RPB, 256>>>(x, b1, b2, b3, Wli, out);
}

// round 13
// speedup vs baseline: 2.4059x; 1.3118x over previous
#include <cuda_runtime.h>
#include <stdint.h>

#define B_   4096
#define F_   1024
#define H_   256
#define C_   10
#define T_   24
#define T2   (T_ - 2)     // steps 22/23 gathers are dead
#define RPB  4

// ---- transposed weights (device globals; no allocation) ----
__device__ __align__(16) float g_W1T[F_ * H_];   // [f][j]
__device__ __align__(16) float g_W2T[H_ * H_];   // [k][j]
__device__ __align__(16) float g_W3T[H_ * H_];   // [k][j]

// ---- packed f32x2 helpers (Blackwell) ----
__device__ __forceinline__ unsigned long long pk2(float lo, float hi) {
    unsigned long long r;
    asm("mov.b64 %0, {%1, %2};" : "=l"(r) : "f"(lo), "f"(hi));
    return r;
}
__device__ __forceinline__ void upk2(unsigned long long v, float& lo, float& hi) {
    asm("mov.b64 {%0, %1}, %2;" : "=f"(lo), "=f"(hi) : "l"(v));
}
__device__ __forceinline__ void addx2(unsigned long long& a, unsigned long long b) {
    asm("add.rn.f32x2 %0, %1, %2;" : "=l"(a) : "l"(a), "l"(b));
}

// per-row-group barrier (64 threads, ids 1..RPB)
#define BARG() asm volatile("bar.sync %0, 64;" :: "r"(barid) : "memory")

// ============================================================
// Tiled transpose of W1/W2/W3 into device globals.
// ============================================================
__global__ void __launch_bounds__(256) transpose_all(
    const float* __restrict__ W1, const float* __restrict__ W2,
    const float* __restrict__ W3) {
    __shared__ float tile[32][33];
    const int zi = blockIdx.z;
    const float* src = (zi == 0) ? W1 : ((zi == 1) ? W2 : W3);
    float* dst = (zi == 0) ? g_W1T : ((zi == 1) ? g_W2T : g_W3T);
    const int C = (zi == 0) ? F_ : H_;
    const int R = H_;
    if ((int)(blockIdx.x * 32) >= C) return;

    const int x = blockIdx.x * 32 + threadIdx.x;
    const int y0 = blockIdx.y * 32;
#pragma unroll
    for (int dy = threadIdx.y; dy < 32; dy += 8)
        tile[dy][threadIdx.x] = src[(size_t)(y0 + dy) * C + x];
    __syncthreads();
    const int x2 = y0 + threadIdx.x;
#pragma unroll
    for (int dy = threadIdx.y; dy < 32; dy += 8)
        dst[(size_t)(blockIdx.x * 32 + dy) * R + x2] = tile[threadIdx.x][dy];
}

// ============================================================
// gather over prescaled byte offsets, 4 accumulator chains, unroll 4
// (PROVEN codegen — do not restructure)
// ============================================================
__device__ __forceinline__ void gatherN(const char* __restrict__ wb,
                                        const uint32_t* __restrict__ lst, int n,
                                        unsigned long long& a01, unsigned long long& a23,
                                        unsigned long long& b01, unsigned long long& b23) {
    int e = 0;
    for (; e + 4 <= n; e += 4) {
        uint4 o = *(const uint4*)(lst + e);
        ulonglong2 w0 = *(const ulonglong2*)(wb + o.x);
        ulonglong2 w1 = *(const ulonglong2*)(wb + o.y);
        ulonglong2 w2 = *(const ulonglong2*)(wb + o.z);
        ulonglong2 w3 = *(const ulonglong2*)(wb + o.w);
        addx2(a01, w0.x); addx2(a23, w0.y);
        addx2(b01, w1.x); addx2(b23, w1.y);
        addx2(a01, w2.x); addx2(a23, w2.y);
        addx2(b01, w3.x); addx2(b23, w3.y);
    }
    for (; e < n; e++) {
        ulonglong2 w = *(const ulonglong2*)(wb + lst[e]);
        addx2(a01, w.x); addx2(a23, w.y);
    }
}

// ============================================================
// Main fused kernel: 2-phase step exploiting the fact that all
// spikes at step t depend only on state from t-1.
//  A (pure ALU): z1/z2/z3 from old state; z-lists; q fold; enc list.
//  B (pure memory): W1[enc]+W2[z1]+W3[z1]+W3[z2] back-to-back,
//    each folded into its current immediately (no cross-barrier
//    gather registers). Dead steps 22/23 elided.
// ============================================================
__global__ void __launch_bounds__(256, 4)
snn_kernel(const float* __restrict__ x,
           const float* __restrict__ b1, const float* __restrict__ b2,
           const float* __restrict__ b3, const float* __restrict__ Wli,
           float* __restrict__ out) {
    __shared__ uint32_t s_bits[RPB][T_][32];                 // 12 KB
    __shared__ __align__(16) uint32_t s_le[2][RPB][512];     // 16 KB (enc offset lists)
    __shared__ __align__(16) uint32_t s_lz[2][RPB][2 * H_];  // 16 KB (z1 @[0,H), z2 @[H,2H))
    __shared__ int s_cntE[2][RPB];
    __shared__ int s_cnt1[2][RPB];
    __shared__ int s_cnt2[2][RPB];
    __shared__ float s_part[RPB][2][C_];

    const int tid = threadIdx.x;
    const int r = tid >> 6;
    const int g = tid & 63;
    const int lane = tid & 31;
    const int j0 = g * 4;
    const int barid = r + 1;
    const int row = blockIdx.x * RPB + r;
    const float* xrow = x + (size_t)row * F_;

    // ---- zero this row's bitmaps & counters (both parities) ----
    for (int i = g; i < T_ * 32; i += 64) ((uint32_t*)s_bits[r])[i] = 0;
    if (g == 0) {
        s_cntE[0][r] = 0; s_cntE[1][r] = 0;
        s_cnt1[0][r] = 0; s_cnt1[1][r] = 0;
        s_cnt2[0][r] = 0; s_cnt2[1][r] = 0;
    }
    BARG();

    // ---- fused encoder -> scatter spikes into per-step bitmaps ----
    {
        const uint32_t mybit = 1u << (g & 31);
        const int wbase = g >> 5;
#pragma unroll 1
        for (int m0 = 0; m0 < 16; m0 += 4) {
            float xv[4], vv[4];
            uint32_t mk[4];
#pragma unroll
            for (int j = 0; j < 4; j++) {
                xv[j] = xrow[g + 64 * (m0 + j)];
                vv[j] = 0.0f; mk[j] = 0u;
            }
#pragma unroll
            for (int t = 0; t < T_; t++) {
#pragma unroll
                for (int j = 0; j < 4; j++) {
                    vv[j] = vv[j] + 0.1f * (xv[j] - vv[j]);
                    if (vv[j] > 1.0f) { mk[j] |= (1u << t); vv[j] = 0.0f; }
                }
            }
#pragma unroll
            for (int j = 0; j < 4; j++) {
                uint32_t m = mk[j];
                const int w = wbase + 2 * (m0 + j);
                while (m) {
                    int t = __ffs(m) - 1; m &= m - 1;
                    atomicOr(&s_bits[r][t][w], mybit);
                }
            }
        }
    }
    BARG();

    const char* W1b = (const char*)g_W1T + (size_t)j0 * 4;
    const char* W2b = (const char*)g_W2T + (size_t)j0 * 4;
    const char* W3b = (const char*)g_W3T + (size_t)j0 * 4;

    float v1[4] = {0,0,0,0}, i1[4] = {0,0,0,0};
    float v2[4] = {0,0,0,0}, i2[4] = {0,0,0,0};
    float v3[4] = {0,0,0,0}, i3[4] = {0,0,0,0};
    float q[4]  = {0,0,0,0};

    // readout coefficients: coef_t = 0.9^(23-t) - 0.8^(23-t)
    float c9 = 1.0f, c8 = 1.0f;
#pragma unroll
    for (int i = 0; i < T_ - 1; i++) { c9 *= 0.9f; c8 *= 0.8f; }

#pragma unroll 1
    for (int t = 0; t < T2; t++) {
        const int p = t & 1;

        // ===== phase A (pure ALU): step-t spikes from old state =====
        {
            if (g == 0) {   // opposite parity: last touched in B(t-1), barrier-separated
                s_cntE[p ^ 1][r] = 0;
                s_cnt1[p ^ 1][r] = 0;
                s_cnt2[p ^ 1][r] = 0;
            }
            int* c1 = &s_cnt1[p][r];
            int* c2 = &s_cnt2[p][r];
            uint32_t* l1 = s_lz[p][r];
            uint32_t* l2 = s_lz[p][r] + H_;
            float coef = c9 - c8;
            c9 *= (1.0f / 0.9f);
            c8 *= 1.25f;
#pragma unroll
            for (int u = 0; u < 4; u++) {
                float vd1 = v1[u] + 0.1f * (i1[u] - v1[u]);
                bool z1 = vd1 > 0.23f;
                v1[u] = z1 ? 0.0f : vd1;
                float vd2 = v2[u] + 0.1f * (i2[u] - v2[u]);
                bool z2 = vd2 > 0.23f;
                v2[u] = z2 ? 0.0f : vd2;
                float vd3 = v3[u] + 0.1f * (i3[u] - v3[u]);
                bool z3 = vd3 > 0.23f;
                v3[u] = z3 ? 0.0f : vd3;
                if (z1) { int pp = atomicAdd(c1, 1); l1[pp] = (uint32_t)((j0 + u) << 10); }
                if (z2) { int pp = atomicAdd(c2, 1); l2[pp] = (uint32_t)((j0 + u) << 10); }
                float o3 = (z1 ? 1.0f : 0.0f) + (z2 ? 1.0f : 0.0f) + (z3 ? 1.0f : 0.0f);
                q[u] = fmaf(coef, o3, q[u]);
            }
            // build enc list for step t: 16-bit halves split over all 64 threads
            {
                const int word = g >> 1;
                const int sh = (g & 1) << 4;
                uint32_t bits = (s_bits[r][t][word] >> sh) & 0xFFFFu;
                const int base = (word << 5) + sh;
                while (bits) {
                    int b = __ffs(bits) - 1; bits &= bits - 1;
                    int pp = atomicAdd(&s_cntE[p][r], 1);
                    s_le[p][r][pp] = (uint32_t)((base + b) << 10);
                }
            }
        }
        BARG();

        // ===== phase B (pure memory): all gathers back-to-back =====
        {
            // W1[enc_t] -> i1
            {
                float4 bv = *(const float4*)(b1 + j0);
                unsigned long long a01 = pk2(bv.x, bv.y), a23 = pk2(bv.z, bv.w);
                unsigned long long d01 = pk2(0.f, 0.f),   d23 = pk2(0.f, 0.f);
                gatherN(W1b, s_le[p][r], s_cntE[p][r], a01, a23, d01, d23);
                addx2(a01, d01); addx2(a23, d23);
                float a[4]; upk2(a01, a[0], a[1]); upk2(a23, a[2], a[3]);
#pragma unroll
                for (int u = 0; u < 4; u++) i1[u] = i1[u] * 0.8f + a[u];
            }
            // W2[z1_t] -> i2
            {
                float4 bv = *(const float4*)(b2 + j0);
                unsigned long long a01 = pk2(bv.x, bv.y), a23 = pk2(bv.z, bv.w);
                unsigned long long d01 = pk2(0.f, 0.f),   d23 = pk2(0.f, 0.f);
                gatherN(W2b, s_lz[p][r], s_cnt1[p][r], a01, a23, d01, d23);
                addx2(a01, d01); addx2(a23, d23);
                float a[4]; upk2(a01, a[0], a[1]); upk2(a23, a[2], a[3]);
#pragma unroll
                for (int u = 0; u < 4; u++) i2[u] = i2[u] * 0.8f + a[u];
            }
            // W3[z1_t] + W3[z2_t] -> i3  (o2 = z1 + z2)
            {
                float4 bv = *(const float4*)(b3 + j0);
                unsigned long long a01 = pk2(bv.x, bv.y), a23 = pk2(bv.z, bv.w);
                unsigned long long d01 = pk2(0.f, 0.f),   d23 = pk2(0.f, 0.f);
                gatherN(W3b, s_lz[p][r], s_cnt1[p][r], a01, a23, d01, d23);
                gatherN(W3b, s_lz[p][r] + H_, s_cnt2[p][r], a01, a23, d01, d23);
                addx2(a01, d01); addx2(a23, d23);
                float a[4]; upk2(a01, a[0], a[1]); upk2(a23, a[2], a[3]);
#pragma unroll
                for (int u = 0; u < 4; u++) i3[u] = i3[u] * 0.8f + a[u];
            }
        }
        BARG();
    }

    // ===== step 22 epilogue: gathers dead; spikes from local state only =====
    {
        float coef = c9 - c8;   // = 0.9 - 0.8 = 0.1
#pragma unroll
        for (int u = 0; u < 4; u++) {
            float vd1 = v1[u] + 0.1f * (i1[u] - v1[u]);
            float vd2 = v2[u] + 0.1f * (i2[u] - v2[u]);
            float vd3 = v3[u] + 0.1f * (i3[u] - v3[u]);
            float o3 = (vd1 > 0.23f ? 1.0f : 0.0f)
                     + (vd2 > 0.23f ? 1.0f : 0.0f)
                     + (vd3 > 0.23f ? 1.0f : 0.0f);
            q[u] = fmaf(coef, o3, q[u]);
        }
    }
    // step 23: output coefficient is exactly 0 -> nothing to do.

    // ---- final readout: out[b][c] = sum_k q_k * Wli[c][k] ----
    const int wig = (tid >> 5) & 1;
#pragma unroll
    for (int c = 0; c < C_; c++) {
        float4 w = *(const float4*)(Wli + c * H_ + j0);
        float s = q[0] * w.x + q[1] * w.y + q[2] * w.z + q[3] * w.w;
#pragma unroll
        for (int off = 16; off; off >>= 1)
            s += __shfl_xor_sync(0xffffffffu, s, off);
        if (lane == 0) s_part[r][wig][c] = s;
    }
    BARG();
    if (g < C_) out[(size_t)row * C_ + g] = s_part[r][0][g] + s_part[r][1][g];
}

// ============================================================
extern "C" void kernel_launch(void* const* d_in, const int* in_sizes, int n_in,
                              void* d_out, int out_size) {
    (void)in_sizes; (void)n_in; (void)out_size;
    const float* x   = (const float*)d_in[0];
    const float* W1  = (const float*)d_in[1];
    const float* b1  = (const float*)d_in[2];
    const float* W2  = (const float*)d_in[3];
    const float* b2  = (const float*)d_in[4];
    const float* W3  = (const float*)d_in[5];
    const float* b3  = (const float*)d_in[6];
    const float* Wli = (const float*)d_in[7];
    float* out = (float*)d_out;

    transpose_all<<<dim3(F_ / 32, H_ / 32, 3), dim3(32, 8)>>>(W1, W2, W3);
    snn_kernel<<<B_ / RPB, 256>>>(x, b1, b2, b3, Wli, out);
}

// round 14
// speedup vs baseline: 2.5030x; 1.0403x over previous
#include <cuda_runtime.h>
#include <stdint.h>

#define B_   4096
#define F_   1024
#define H_   256
#define C_   10
#define T_   24
#define T2   (T_ - 2)     // steps 22/23 gathers are dead
#define RPB  4
#define EMAX 512          // max spiking encoder elements per row (mean ~141, 34 sigma)

// ---- transposed weights (device globals; no allocation) ----
__device__ __align__(16) float g_W1T[F_ * H_];   // [f][j]
__device__ __align__(16) float g_W2T[H_ * H_];   // [k][j]
__device__ __align__(16) float g_W3T[H_ * H_];   // [k][j]

// ---- packed f32x2 helpers (Blackwell) ----
__device__ __forceinline__ unsigned long long pk2(float lo, float hi) {
    unsigned long long r;
    asm("mov.b64 %0, {%1, %2};" : "=l"(r) : "f"(lo), "f"(hi));
    return r;
}
__device__ __forceinline__ void upk2(unsigned long long v, float& lo, float& hi) {
    asm("mov.b64 {%0, %1}, %2;" : "=f"(lo), "=f"(hi) : "l"(v));
}
__device__ __forceinline__ void addx2(unsigned long long& a, unsigned long long b) {
    asm("add.rn.f32x2 %0, %1, %2;" : "=l"(a) : "l"(a), "l"(b));
}

// per-row-group barrier (64 threads, ids 1..RPB)
#define BARG() asm volatile("bar.sync %0, 64;" :: "r"(barid) : "memory")

// ============================================================
// Tiled transpose of W1/W2/W3 into device globals.
// ============================================================
__global__ void __launch_bounds__(256) transpose_all(
    const float* __restrict__ W1, const float* __restrict__ W2,
    const float* __restrict__ W3) {
    __shared__ float tile[32][33];
    const int zi = blockIdx.z;
    const float* src = (zi == 0) ? W1 : ((zi == 1) ? W2 : W3);
    float* dst = (zi == 0) ? g_W1T : ((zi == 1) ? g_W2T : g_W3T);
    const int C = (zi == 0) ? F_ : H_;
    const int R = H_;
    if ((int)(blockIdx.x * 32) >= C) return;

    const int x = blockIdx.x * 32 + threadIdx.x;
    const int y0 = blockIdx.y * 32;
#pragma unroll
    for (int dy = threadIdx.y; dy < 32; dy += 8)
        tile[dy][threadIdx.x] = src[(size_t)(y0 + dy) * C + x];
    __syncthreads();
    const int x2 = y0 + threadIdx.x;
#pragma unroll
    for (int dy = threadIdx.y; dy < 32; dy += 8)
        dst[(size_t)(blockIdx.x * 32 + dy) * R + x2] = tile[threadIdx.x][dy];
}

// ============================================================
// gather over prescaled byte offsets, 4 accumulator chains, unroll 4
// (PROVEN codegen — do not restructure)
// ============================================================
__device__ __forceinline__ void gatherN(const char* __restrict__ wb,
                                        const uint32_t* __restrict__ lst, int n,
                                        unsigned long long& a01, unsigned long long& a23,
                                        unsigned long long& b01, unsigned long long& b23) {
    int e = 0;
    for (; e + 4 <= n; e += 4) {
        uint4 o = *(const uint4*)(lst + e);
        ulonglong2 w0 = *(const ulonglong2*)(wb + o.x);
        ulonglong2 w1 = *(const ulonglong2*)(wb + o.y);
        ulonglong2 w2 = *(const ulonglong2*)(wb + o.z);
        ulonglong2 w3 = *(const ulonglong2*)(wb + o.w);
        addx2(a01, w0.x); addx2(a23, w0.y);
        addx2(b01, w1.x); addx2(b23, w1.y);
        addx2(a01, w2.x); addx2(a23, w2.y);
        addx2(b01, w3.x); addx2(b23, w3.y);
    }
    for (; e < n; e++) {
        ulonglong2 w = *(const ulonglong2*)(wb + lst[e]);
        addx2(a01, w.x); addx2(a23, w.y);
    }
}

// ============================================================
// Main fused kernel (R13 A/B structure) + compacted encoder:
// elements with x < 1.08 provably never spike (v_max <= x*0.92005
// plus ~2e-6 fp32 drift << 1.0) -> only spiking candidates (~14%)
// run the exact 24-step fp32 iteration, cooperatively over a
// compacted smem list. Bit-exact vs reference encoder.
//  A (pure ALU): z1/z2/z3 from old state; z-lists; q fold; enc list.
//  B (pure memory): W1[enc]+W2[z1]+W3[z1]+W3[z2] back-to-back.
// Dead steps 22/23 elided. Lists single-buffered (write A(t),
// read B(t), overwrite A(t+1) — barrier-separated); counters
// double-buffered.
// ============================================================
__global__ void __launch_bounds__(256, 4)
snn_kernel(const float* __restrict__ x,
           const float* __restrict__ b1, const float* __restrict__ b2,
           const float* __restrict__ b3, const float* __restrict__ Wli,
           float* __restrict__ out) {
    __shared__ uint32_t s_bits[RPB][T_][32];                 // 12 KB
    __shared__ __align__(16) uint32_t s_le[RPB][512];        // 8 KB (enc offset list)
    __shared__ __align__(16) uint32_t s_lz[RPB][2 * H_];     // 8 KB (z1 @[0,H), z2 @[H,2H))
    __shared__ __align__(16) float    s_ex[RPB][EMAX];       // 8 KB (spiking x values)
    __shared__ uint16_t s_ef[RPB][EMAX];                     // 4 KB (their feature idx)
    __shared__ int s_ecnt[RPB];
    __shared__ int s_cntE[2][RPB];
    __shared__ int s_cnt1[2][RPB];
    __shared__ int s_cnt2[2][RPB];
    __shared__ float s_part[RPB][2][C_];

    const int tid = threadIdx.x;
    const int r = tid >> 6;
    const int g = tid & 63;
    const int lane = tid & 31;
    const int j0 = g * 4;
    const int barid = r + 1;
    const int row = blockIdx.x * RPB + r;
    const float* xrow = x + (size_t)row * F_;

    // ---- zero this row's bitmaps & counters (both parities) ----
    for (int i = g; i < T_ * 32; i += 64) ((uint32_t*)s_bits[r])[i] = 0;
    if (g == 0) {
        s_ecnt[r] = 0;
        s_cntE[0][r] = 0; s_cntE[1][r] = 0;
        s_cnt1[0][r] = 0; s_cnt1[1][r] = 0;
        s_cnt2[0][r] = 0; s_cnt2[1][r] = 0;
    }
    BARG();

    // ---- encoder stage 1: compact spiking candidates (x >= 1.08) ----
    {
#pragma unroll
        for (int m = 0; m < 16; m++) {
            const int f = g + 64 * m;
            float xv = xrow[f];
            if (xv >= 1.08f) {
                int p = atomicAdd(&s_ecnt[r], 1);
                if (p < EMAX) { s_ex[r][p] = xv; s_ef[r][p] = (uint16_t)f; }
            }
        }
    }
    BARG();

    // ---- encoder stage 2: exact 24-step fp32 LIF on compacted list ----
    {
        const int ne = s_ecnt[r];
        for (int i = g; i < ne; i += 64) {
            const float xv = s_ex[r][i];
            const int f = s_ef[r][i];
            const uint32_t bit = 1u << (f & 31);
            const int w = f >> 5;
            float v = 0.0f;
#pragma unroll
            for (int t = 0; t < T_; t++) {
                v = v + 0.1f * (xv - v);
                if (v > 1.0f) { atomicOr(&s_bits[r][t][w], bit); v = 0.0f; }
            }
        }
    }
    BARG();

    const char* W1b = (const char*)g_W1T + (size_t)j0 * 4;
    const char* W2b = (const char*)g_W2T + (size_t)j0 * 4;
    const char* W3b = (const char*)g_W3T + (size_t)j0 * 4;

    float v1[4] = {0,0,0,0}, i1[4] = {0,0,0,0};
    float v2[4] = {0,0,0,0}, i2[4] = {0,0,0,0};
    float v3[4] = {0,0,0,0}, i3[4] = {0,0,0,0};
    float q[4]  = {0,0,0,0};

    // readout coefficients: coef_t = 0.9^(23-t) - 0.8^(23-t)
    float c9 = 1.0f, c8 = 1.0f;
#pragma unroll
    for (int i = 0; i < T_ - 1; i++) { c9 *= 0.9f; c8 *= 0.8f; }

#pragma unroll 1
    for (int t = 0; t < T2; t++) {
        const int p = t & 1;

        // ===== phase A (pure ALU): step-t spikes from old state =====
        {
            if (g == 0) {   // opposite parity: last read in B(t-1), barrier-separated
                s_cntE[p ^ 1][r] = 0;
                s_cnt1[p ^ 1][r] = 0;
                s_cnt2[p ^ 1][r] = 0;
            }
            int* c1 = &s_cnt1[p][r];
            int* c2 = &s_cnt2[p][r];
            uint32_t* l1 = s_lz[r];
            uint32_t* l2 = s_lz[r] + H_;
            float coef = c9 - c8;
            c9 *= (1.0f / 0.9f);
            c8 *= 1.25f;
#pragma unroll
            for (int u = 0; u < 4; u++) {
                float vd1 = v1[u] + 0.1f * (i1[u] - v1[u]);
                bool z1 = vd1 > 0.23f;
                v1[u] = z1 ? 0.0f : vd1;
                float vd2 = v2[u] + 0.1f * (i2[u] - v2[u]);
                bool z2 = vd2 > 0.23f;
                v2[u] = z2 ? 0.0f : vd2;
                float vd3 = v3[u] + 0.1f * (i3[u] - v3[u]);
                bool z3 = vd3 > 0.23f;
                v3[u] = z3 ? 0.0f : vd3;
                if (z1) { int pp = atomicAdd(c1, 1); l1[pp] = (uint32_t)((j0 + u) << 10); }
                if (z2) { int pp = atomicAdd(c2, 1); l2[pp] = (uint32_t)((j0 + u) << 10); }
                float o3 = (z1 ? 1.0f : 0.0f) + (z2 ? 1.0f : 0.0f) + (z3 ? 1.0f : 0.0f);
                q[u] = fmaf(coef, o3, q[u]);
            }
            // build enc list for step t: 16-bit halves split over all 64 threads
            {
                const int word = g >> 1;
                const int sh = (g & 1) << 4;
                uint32_t bits = (s_bits[r][t][word] >> sh) & 0xFFFFu;
                const int base = (word << 5) + sh;
                while (bits) {
                    int b = __ffs(bits) - 1; bits &= bits - 1;
                    int pp = atomicAdd(&s_cntE[p][r], 1);
                    s_le[r][pp] = (uint32_t)((base + b) << 10);
                }
            }
        }
        BARG();

        // ===== phase B (pure memory): all gathers back-to-back =====
        {
            // W1[enc_t] -> i1
            {
                float4 bv = *(const float4*)(b1 + j0);
                unsigned long long a01 = pk2(bv.x, bv.y), a23 = pk2(bv.z, bv.w);
                unsigned long long d01 = pk2(0.f, 0.f),   d23 = pk2(0.f, 0.f);
                gatherN(W1b, s_le[r], s_cntE[p][r], a01, a23, d01, d23);
                addx2(a01, d01); addx2(a23, d23);
                float a[4]; upk2(a01, a[0], a[1]); upk2(a23, a[2], a[3]);
#pragma unroll
                for (int u = 0; u < 4; u++) i1[u] = i1[u] * 0.8f + a[u];
            }
            // W2[z1_t] -> i2
            {
                float4 bv = *(const float4*)(b2 + j0);
                unsigned long long a01 = pk2(bv.x, bv.y), a23 = pk2(bv.z, bv.w);
                unsigned long long d01 = pk2(0.f, 0.f),   d23 = pk2(0.f, 0.f);
                gatherN(W2b, s_lz[r], s_cnt1[p][r], a01, a23, d01, d23);
                addx2(a01, d01); addx2(a23, d23);
                float a[4]; upk2(a01, a[0], a[1]); upk2(a23, a[2], a[3]);
#pragma unroll
                for (int u = 0; u < 4; u++) i2[u] = i2[u] * 0.8f + a[u];
            }
            // W3[z1_t] + W3[z2_t] -> i3  (o2 = z1 + z2)
            {
                float4 bv = *(const float4*)(b3 + j0);
                unsigned long long a01 = pk2(bv.x, bv.y), a23 = pk2(bv.z, bv.w);
                unsigned long long d01 = pk2(0.f, 0.f),   d23 = pk2(0.f, 0.f);
                gatherN(W3b, s_lz[r], s_cnt1[p][r], a01, a23, d01, d23);
                gatherN(W3b, s_lz[r] + H_, s_cnt2[p][r], a01, a23, d01, d23);
                addx2(a01, d01); addx2(a23, d23);
                float a[4]; upk2(a01, a[0], a[1]); upk2(a23, a[2], a[3]);
#pragma unroll
                for (int u = 0; u < 4; u++) i3[u] = i3[u] * 0.8f + a[u];
            }
        }
        BARG();
    }

    // ===== step 22 epilogue: gathers dead; spikes from local state only =====
    {
        float coef = c9 - c8;   // = 0.9 - 0.8 = 0.1
#pragma unroll
        for (int u = 0; u < 4; u++) {
            float vd1 = v1[u] + 0.1f * (i1[u] - v1[u]);
            float vd2 = v2[u] + 0.1f * (i2[u] - v2[u]);
            float vd3 = v3[u] + 0.1f * (i3[u] - v3[u]);
            float o3 = (vd1 > 0.23f ? 1.0f : 0.0f)
                     + (vd2 > 0.23f ? 1.0f : 0.0f)
                     + (vd3 > 0.23f ? 1.0f : 0.0f);
            q[u] = fmaf(coef, o3, q[u]);
        }
    }
    // step 23: output coefficient is exactly 0 -> nothing to do.

    // ---- final readout: out[b][c] = sum_k q_k * Wli[c][k] ----
    const int wig = (tid >> 5) & 1;
#pragma unroll
    for (int c = 0; c < C_; c++) {
        float4 w = *(const float4*)(Wli + c * H_ + j0);
        float s = q[0] * w.x + q[1] * w.y + q[2] * w.z + q[3] * w.w;
#pragma unroll
        for (int off = 16; off; off >>= 1)
            s += __shfl_xor_sync(0xffffffffu, s, off);
        if (lane == 0) s_part[r][wig][c] = s;
    }
    BARG();
    if (g < C_) out[(size_t)row * C_ + g] = s_part[r][0][g] + s_part[r][1][g];
}

// ============================================================
extern "C" void kernel_launch(void* const* d_in, const int* in_sizes, int n_in,
                              void* d_out, int out_size) {
    (void)in_sizes; (void)n_in; (void)out_size;
    const float* x   = (const float*)d_in[0];
    const float* W1  = (const float*)d_in[1];
    const float* b1  = (const float*)d_in[2];
    const float* W2  = (const float*)d_in[3];
    const float* b2  = (const float*)d_in[4];
    const float* W3  = (const float*)d_in[5];
    const float* b3  = (const float*)d_in[6];
    const float* Wli = (const float*)d_in[7];
    float* out = (float*)d_out;

    transpose_all<<<dim3(F_ / 32, H_ / 32, 3), dim3(32, 8)>>>(W1, W2, W3);
    snn_kernel<<<B_ / RPB, 256>>>(x, b1, b2, b3, Wli, out);
}

// round 15
// speedup vs baseline: 2.7958x; 1.1170x over previous
#include <cuda_runtime.h>
#include <stdint.h>

#define B_   4096
#define F_   1024
#define H_   256
#define C_   10
#define T_   24
#define T2   (T_ - 2)     // steps 22/23 gathers are dead
#define RPB  4
#define EMAX 512          // max spiking encoder elements per row (mean ~141)

// ---- transposed weights (device globals; no allocation) ----
__device__ __align__(16) float g_W1T[F_ * H_];   // [f][j]
__device__ __align__(16) float g_W2T[H_ * H_];   // [k][j]
__device__ __align__(16) float g_W3T[H_ * H_];   // [k][j]

// ---- packed f32x2 helpers (Blackwell) ----
__device__ __forceinline__ unsigned long long pk2(float lo, float hi) {
    unsigned long long r;
    asm("mov.b64 %0, {%1, %2};" : "=l"(r) : "f"(lo), "f"(hi));
    return r;
}
__device__ __forceinline__ void upk2(unsigned long long v, float& lo, float& hi) {
    asm("mov.b64 {%0, %1}, %2;" : "=f"(lo), "=f"(hi) : "l"(v));
}
__device__ __forceinline__ void addx2(unsigned long long& a, unsigned long long b) {
    asm("add.rn.f32x2 %0, %1, %2;" : "=l"(a) : "l"(a), "l"(b));
}

// per-row-group barrier (64 threads, ids 1..RPB)
#define BARG() asm volatile("bar.sync %0, 64;" :: "r"(barid) : "memory")

// ============================================================
// Tiled transpose of W1/W2/W3 into device globals.
// ============================================================
__global__ void __launch_bounds__(256) transpose_all(
    const float* __restrict__ W1, const float* __restrict__ W2,
    const float* __restrict__ W3) {
    __shared__ float tile[32][33];
    const int zi = blockIdx.z;
    const float* src = (zi == 0) ? W1 : ((zi == 1) ? W2 : W3);
    float* dst = (zi == 0) ? g_W1T : ((zi == 1) ? g_W2T : g_W3T);
    const int C = (zi == 0) ? F_ : H_;
    const int R = H_;
    if ((int)(blockIdx.x * 32) >= C) return;

    const int x = blockIdx.x * 32 + threadIdx.x;
    const int y0 = blockIdx.y * 32;
#pragma unroll
    for (int dy = threadIdx.y; dy < 32; dy += 8)
        tile[dy][threadIdx.x] = src[(size_t)(y0 + dy) * C + x];
    __syncthreads();
    const int x2 = y0 + threadIdx.x;
#pragma unroll
    for (int dy = threadIdx.y; dy < 32; dy += 8)
        dst[(size_t)(blockIdx.x * 32 + dy) * R + x2] = tile[threadIdx.x][dy];
}

// ============================================================
// gather over prescaled byte offsets, 4 accumulator chains, unroll 4
// (PROVEN codegen — do not restructure)
// ============================================================
__device__ __forceinline__ void gatherN(const char* __restrict__ wb,
                                        const uint32_t* __restrict__ lst, int n,
                                        unsigned long long& a01, unsigned long long& a23,
                                        unsigned long long& b01, unsigned long long& b23) {
    int e = 0;
    for (; e + 4 <= n; e += 4) {
        uint4 o = *(const uint4*)(lst + e);
        ulonglong2 w0 = *(const ulonglong2*)(wb + o.x);
        ulonglong2 w1 = *(const ulonglong2*)(wb + o.y);
        ulonglong2 w2 = *(const ulonglong2*)(wb + o.z);
        ulonglong2 w3 = *(const ulonglong2*)(wb + o.w);
        addx2(a01, w0.x); addx2(a23, w0.y);
        addx2(b01, w1.x); addx2(b23, w1.y);
        addx2(a01, w2.x); addx2(a23, w2.y);
        addx2(b01, w3.x); addx2(b23, w3.y);
    }
    for (; e < n; e++) {
        ulonglong2 w = *(const ulonglong2*)(wb + lst[e]);
        addx2(a01, w.x); addx2(a23, w.y);
    }
}

// ============================================================
// Main fused kernel (R14 structure: A/B phases, compacted encoder)
// with phase B's W2[z1] and W3[z1] loops FUSED into one dual loop
// over the shared z1 list (one index read feeds both matrices;
// drains 4 -> 3 per step). No accumulators cross any barrier.
// Dead steps 22/23 elided.
// ============================================================
__global__ void __launch_bounds__(256, 4)
snn_kernel(const float* __restrict__ x,
           const float* __restrict__ b1, const float* __restrict__ b2,
           const float* __restrict__ b3, const float* __restrict__ Wli,
           float* __restrict__ out) {
    __shared__ uint32_t s_bits[RPB][T_][32];                 // 12 KB
    __shared__ __align__(16) uint32_t s_le[RPB][512];        // 8 KB (enc offset list)
    __shared__ __align__(16) uint32_t s_lz[RPB][2 * H_];     // 8 KB (z1 @[0,H), z2 @[H,2H))
    __shared__ __align__(16) float    s_ex[RPB][EMAX];       // 8 KB (spiking x values)
    __shared__ uint16_t s_ef[RPB][EMAX];                     // 4 KB (their feature idx)
    __shared__ int s_ecnt[RPB];
    __shared__ int s_cntE[2][RPB];
    __shared__ int s_cnt1[2][RPB];
    __shared__ int s_cnt2[2][RPB];
    __shared__ float s_part[RPB][2][C_];

    const int tid = threadIdx.x;
    const int r = tid >> 6;
    const int g = tid & 63;
    const int lane = tid & 31;
    const int j0 = g * 4;
    const int barid = r + 1;
    const int row = blockIdx.x * RPB + r;
    const float* xrow = x + (size_t)row * F_;

    // ---- zero this row's bitmaps & counters (both parities) ----
    for (int i = g; i < T_ * 32; i += 64) ((uint32_t*)s_bits[r])[i] = 0;
    if (g == 0) {
        s_ecnt[r] = 0;
        s_cntE[0][r] = 0; s_cntE[1][r] = 0;
        s_cnt1[0][r] = 0; s_cnt1[1][r] = 0;
        s_cnt2[0][r] = 0; s_cnt2[1][r] = 0;
    }
    BARG();

    // ---- encoder stage 1: compact spiking candidates (x >= 1.08) ----
    {
#pragma unroll
        for (int m = 0; m < 16; m++) {
            const int f = g + 64 * m;
            float xv = xrow[f];
            if (xv >= 1.08f) {
                int p = atomicAdd(&s_ecnt[r], 1);
                if (p < EMAX) { s_ex[r][p] = xv; s_ef[r][p] = (uint16_t)f; }
            }
        }
    }
    BARG();

    // ---- encoder stage 2: exact 24-step fp32 LIF on compacted list ----
    {
        const int ne = s_ecnt[r];
        for (int i = g; i < ne; i += 64) {
            const float xv = s_ex[r][i];
            const int f = s_ef[r][i];
            const uint32_t bit = 1u << (f & 31);
            const int w = f >> 5;
            float v = 0.0f;
#pragma unroll
            for (int t = 0; t < T_; t++) {
                v = v + 0.1f * (xv - v);
                if (v > 1.0f) { atomicOr(&s_bits[r][t][w], bit); v = 0.0f; }
            }
        }
    }
    BARG();

    const char* W1b = (const char*)g_W1T + (size_t)j0 * 4;
    const char* W2b = (const char*)g_W2T + (size_t)j0 * 4;
    const char* W3b = (const char*)g_W3T + (size_t)j0 * 4;

    float v1[4] = {0,0,0,0}, i1[4] = {0,0,0,0};
    float v2[4] = {0,0,0,0}, i2[4] = {0,0,0,0};
    float v3[4] = {0,0,0,0}, i3[4] = {0,0,0,0};
    float q[4]  = {0,0,0,0};

    // readout coefficients: coef_t = 0.9^(23-t) - 0.8^(23-t)
    float c9 = 1.0f, c8 = 1.0f;
#pragma unroll
    for (int i = 0; i < T_ - 1; i++) { c9 *= 0.9f; c8 *= 0.8f; }

#pragma unroll 1
    for (int t = 0; t < T2; t++) {
        const int p = t & 1;

        // ===== phase A (pure ALU): step-t spikes from old state =====
        {
            if (g == 0) {   // opposite parity: last read in B(t-1), barrier-separated
                s_cntE[p ^ 1][r] = 0;
                s_cnt1[p ^ 1][r] = 0;
                s_cnt2[p ^ 1][r] = 0;
            }
            int* c1 = &s_cnt1[p][r];
            int* c2 = &s_cnt2[p][r];
            uint32_t* l1 = s_lz[r];
            uint32_t* l2 = s_lz[r] + H_;
            float coef = c9 - c8;
            c9 *= (1.0f / 0.9f);
            c8 *= 1.25f;
#pragma unroll
            for (int u = 0; u < 4; u++) {
                float vd1 = v1[u] + 0.1f * (i1[u] - v1[u]);
                bool z1 = vd1 > 0.23f;
                v1[u] = z1 ? 0.0f : vd1;
                float vd2 = v2[u] + 0.1f * (i2[u] - v2[u]);
                bool z2 = vd2 > 0.23f;
                v2[u] = z2 ? 0.0f : vd2;
                float vd3 = v3[u] + 0.1f * (i3[u] - v3[u]);
                bool z3 = vd3 > 0.23f;
                v3[u] = z3 ? 0.0f : vd3;
                if (z1) { int pp = atomicAdd(c1, 1); l1[pp] = (uint32_t)((j0 + u) << 10); }
                if (z2) { int pp = atomicAdd(c2, 1); l2[pp] = (uint32_t)((j0 + u) << 10); }
                float o3 = (z1 ? 1.0f : 0.0f) + (z2 ? 1.0f : 0.0f) + (z3 ? 1.0f : 0.0f);
                q[u] = fmaf(coef, o3, q[u]);
            }
            // build enc list for step t: 16-bit halves split over all 64 threads
            {
                const int word = g >> 1;
                const int sh = (g & 1) << 4;
                uint32_t bits = (s_bits[r][t][word] >> sh) & 0xFFFFu;
                const int base = (word << 5) + sh;
                while (bits) {
                    int b = __ffs(bits) - 1; bits &= bits - 1;
                    int pp = atomicAdd(&s_cntE[p][r], 1);
                    s_le[r][pp] = (uint32_t)((base + b) << 10);
                }
            }
        }
        BARG();

        // ===== phase B (pure memory): gathers back-to-back =====
        {
            // W1[enc_t] -> i1
            {
                float4 bv = *(const float4*)(b1 + j0);
                unsigned long long a01 = pk2(bv.x, bv.y), a23 = pk2(bv.z, bv.w);
                unsigned long long d01 = pk2(0.f, 0.f),   d23 = pk2(0.f, 0.f);
                gatherN(W1b, s_le[r], s_cntE[p][r], a01, a23, d01, d23);
                addx2(a01, d01); addx2(a23, d23);
                float a[4]; upk2(a01, a[0], a[1]); upk2(a23, a[2], a[3]);
#pragma unroll
                for (int u = 0; u < 4; u++) i1[u] = i1[u] * 0.8f + a[u];
            }
            // FUSED dual loop over z1: W2[z1] -> a-chains, W3[z1] -> c-chains
            // then W3[z2] -> d-chains merged into c. i2 from a, i3 from c.
            {
                float4 bv2 = *(const float4*)(b2 + j0);
                float4 bv3 = *(const float4*)(b3 + j0);
                unsigned long long a01 = pk2(bv2.x, bv2.y), a23 = pk2(bv2.z, bv2.w);
                unsigned long long c01 = pk2(bv3.x, bv3.y), c23 = pk2(bv3.z, bv3.w);
                const uint32_t* lz = s_lz[r];
                const int n1 = s_cnt1[p][r];
                int e = 0;
                for (; e + 2 <= n1; e += 2) {
                    uint2 o = *(const uint2*)(lz + e);
                    ulonglong2 wa0 = *(const ulonglong2*)(W2b + o.x);
                    ulonglong2 wc0 = *(const ulonglong2*)(W3b + o.x);
                    ulonglong2 wa1 = *(const ulonglong2*)(W2b + o.y);
                    ulonglong2 wc1 = *(const ulonglong2*)(W3b + o.y);
                    addx2(a01, wa0.x); addx2(a23, wa0.y);
                    addx2(c01, wc0.x); addx2(c23, wc0.y);
                    addx2(a01, wa1.x); addx2(a23, wa1.y);
                    addx2(c01, wc1.x); addx2(c23, wc1.y);
                }
                if (e < n1) {
                    uint32_t o = lz[e];
                    ulonglong2 wa = *(const ulonglong2*)(W2b + o);
                    ulonglong2 wc = *(const ulonglong2*)(W3b + o);
                    addx2(a01, wa.x); addx2(a23, wa.y);
                    addx2(c01, wc.x); addx2(c23, wc.y);
                }
                // W3[z2_t] into fresh chains, then fold into c
                {
                    unsigned long long d01 = pk2(0.f, 0.f), d23 = pk2(0.f, 0.f);
                    unsigned long long e01 = pk2(0.f, 0.f), e23 = pk2(0.f, 0.f);
                    gatherN(W3b, s_lz[r] + H_, s_cnt2[p][r], d01, d23, e01, e23);
                    addx2(d01, e01); addx2(d23, e23);
                    addx2(c01, d01); addx2(c23, d23);
                }
                float a[4]; upk2(a01, a[0], a[1]); upk2(a23, a[2], a[3]);
                float c[4]; upk2(c01, c[0], c[1]); upk2(c23, c[2], c[3]);
#pragma unroll
                for (int u = 0; u < 4; u++) {
                    i2[u] = i2[u] * 0.8f + a[u];
                    i3[u] = i3[u] * 0.8f + c[u];
                }
            }
        }
        BARG();
    }

    // ===== step 22 epilogue: gathers dead; spikes from local state only =====
    {
        float coef = c9 - c8;   // = 0.9 - 0.8 = 0.1
#pragma unroll
        for (int u = 0; u < 4; u++) {
            float vd1 = v1[u] + 0.1f * (i1[u] - v1[u]);
            float vd2 = v2[u] + 0.1f * (i2[u] - v2[u]);
            float vd3 = v3[u] + 0.1f * (i3[u] - v3[u]);
            float o3 = (vd1 > 0.23f ? 1.0f : 0.0f)
                     + (vd2 > 0.23f ? 1.0f : 0.0f)
                     + (vd3 > 0.23f ? 1.0f : 0.0f);
            q[u] = fmaf(coef, o3, q[u]);
        }
    }
    // step 23: output coefficient is exactly 0 -> nothing to do.

    // ---- final readout: out[b][c] = sum_k q_k * Wli[c][k] ----
    const int wig = (tid >> 5) & 1;
#pragma unroll
    for (int c = 0; c < C_; c++) {
        float4 w = *(const float4*)(Wli + c * H_ + j0);
        float s = q[0] * w.x + q[1] * w.y + q[2] * w.z + q[3] * w.w;
#pragma unroll
        for (int off = 16; off; off >>= 1)
            s += __shfl_xor_sync(0xffffffffu, s, off);
        if (lane == 0) s_part[r][wig][c] = s;
    }
    BARG();
    if (g < C_) out[(size_t)row * C_ + g] = s_part[r][0][g] + s_part[r][1][g];
}

// ============================================================
extern "C" void kernel_launch(void* const* d_in, const int* in_sizes, int n_in,
                              void* d_out, int out_size) {
    (void)in_sizes; (void)n_in; (void)out_size;
    const float* x   = (const float*)d_in[0];
    const float* W1  = (const float*)d_in[1];
    const float* b1  = (const float*)d_in[2];
    const float* W2  = (const float*)d_in[3];
    const float* b2  = (const float*)d_in[4];
    const float* W3  = (const float*)d_in[5];
    const float* b3  = (const float*)d_in[6];
    const float* Wli = (const float*)d_in[7];
    float* out = (float*)d_out;

    transpose_all<<<dim3(F_ / 32, H_ / 32, 3), dim3(32, 8)>>>(W1, W2, W3);
    snn_kernel<<<B_ / RPB, 256>>>(x, b1, b2, b3, Wli, out);
}